// round 1
// baseline (speedup 1.0000x reference)
#include <cuda_runtime.h>

#define B_  512
#define T_  512
#define F_  128
#define NU  50
#define NC  150   // 3*NU
#define XP  160   // padded X row (float)

// Scratch for the projected inputs X[b][t][160] (cols 150..159 are pad garbage).
__device__ float g_X[(size_t)B_ * T_ * XP];

// ---------------- packed f32x2 helpers ----------------
__device__ __forceinline__ unsigned long long dup2(float x) {
    unsigned long long r;
    asm("mov.b64 %0, {%1, %1};" : "=l"(r) : "f"(x));
    return r;
}
__device__ __forceinline__ void fma2(unsigned long long& d, unsigned long long a, unsigned long long b) {
    asm("fma.rn.f32x2 %0, %1, %2, %0;" : "+l"(d) : "l"(a), "l"(b));
}

__device__ __forceinline__ float sigm(float x) {
    return __fdividef(1.f, 1.f + __expf(-x));
}
__device__ __forceinline__ float tanh_fast(float x) {
    return __fdividef(2.f, 1.f + __expf(-2.f * x)) - 1.f;
}

// ---------------- Kernel 1: input projection ----------------
// One CTA per batch element b. Weff[k][c] = W[k][c] * dp[c/50][b][k] in smem.
// Thread tile: 2 rows (timesteps) x 10 cols, via fma.rn.f32x2 (5 col-pairs).
#define XT_ROWS 32
#define AS 36                      // A_s row pad (floats)
#define SM_W  (F_ * XP)
#define SM_BI (XP)
#define SM_A  (F_ * AS)
#define SMEM_XPROJ ((SM_W + SM_BI + SM_A) * 4)

__global__ void __launch_bounds__(256, 2) xproj_kernel(
    const float* __restrict__ inp, const float* __restrict__ W,
    const float* __restrict__ bb, const float* __restrict__ dp)
{
    extern __shared__ float sm[];
    float* Weff = sm;              // [128][160]
    float* bi_s = sm + SM_W;       // [160]
    float* A_s  = bi_s + SM_BI;    // [128][36] (k-major, transposed tile)

    const int b = blockIdx.x;
    const int tid = threadIdx.x;

    // Build masked-weight matrix for this batch element (+ zero pad cols)
    for (int idx = tid; idx < F_ * XP; idx += 256) {
        int k = idx / XP, c = idx - k * XP;
        float w = 0.f;
        if (c < NC) w = W[k * NC + c] * dp[(c / NU) * (B_ * F_) + b * F_ + k];
        Weff[idx] = w;
    }
    for (int c = tid; c < XP; c += 256)
        bi_s[c] = (c < NC) ? bb[c] : 0.f;

    const int cx = tid & 15;        // 16 col groups of 10 cols
    const int ry = tid >> 4;        // 16 row groups of 2 rows
    const int c0 = cx * 10;
    const int r0 = ry * 2;
    const unsigned long long* Wv = reinterpret_cast<const unsigned long long*>(Weff);
    const unsigned long long* bv = reinterpret_cast<const unsigned long long*>(bi_s);

    for (int tile = 0; tile < T_ / XT_ROWS; ++tile) {
        const int t0 = tile * XT_ROWS;
        __syncthreads();   // protect A_s reuse (also covers Weff build on tile 0)
        const float* src = inp + ((size_t)b * T_ + t0) * F_;
        for (int e = tid; e < XT_ROWS * F_; e += 256) {
            int r = e >> 7, k = e & 127;
            A_s[k * AS + r] = src[r * F_ + k];
        }
        __syncthreads();

        unsigned long long acc0[5], acc1[5];
        #pragma unroll
        for (int j = 0; j < 5; ++j) { acc0[j] = bv[c0 / 2 + j]; acc1[j] = acc0[j]; }

        #pragma unroll 4
        for (int k = 0; k < F_; ++k) {
            unsigned long long A0 = dup2(A_s[k * AS + r0]);
            unsigned long long A1 = dup2(A_s[k * AS + r0 + 1]);
            #pragma unroll
            for (int j = 0; j < 5; ++j) {
                unsigned long long w = Wv[k * (XP / 2) + c0 / 2 + j];
                fma2(acc0[j], A0, w);
                fma2(acc1[j], A1, w);
            }
        }
        unsigned long long* X0 = reinterpret_cast<unsigned long long*>(
            g_X + ((size_t)b * T_ + t0 + r0) * XP + c0);
        unsigned long long* X1 = reinterpret_cast<unsigned long long*>(
            g_X + ((size_t)b * T_ + t0 + r0 + 1) * XP + c0);
        #pragma unroll
        for (int j = 0; j < 5; ++j) { X0[j] = acc0[j]; X1[j] = acc1[j]; }
    }
}

// ---------------- Kernel 2: recurrent scan ----------------
// 128 CTAs x 4 batch rows each; rows are fully independent across CTAs.
// Thread (u, s): unit u (u<50), split-K half s over j. U packed float4{Uz,Ur,Uh}.
// h kept in registers; broadcast via hmpk float4{h*rdp0, h*rdp1, h*rdp2, h}.
__global__ void __launch_bounds__(128, 1) scan_kernel(
    const float* __restrict__ U, const float* __restrict__ bb,
    const float* __restrict__ Wd, const float* __restrict__ bd,
    const float* __restrict__ rdp, float* __restrict__ out)
{
    __shared__ float4 Upk[NU * NU];   // [j][u]
    __shared__ float4 hmpk[4][NU];    // per-row masked h broadcast
    __shared__ float4 part[4][NU];    // split-K partials / final reduce

    const int tid = threadIdx.x;
    const int s = tid >> 6;          // 0/1 : j-half
    const int u = tid & 63;          // unit (active if < 50)
    const int b0 = blockIdx.x * 4;
    const bool active = (u < NU);

    for (int idx = tid; idx < NU * NU; idx += 128) {
        int j = idx / NU, uu = idx - j * NU;
        Upk[idx] = make_float4(U[j * NC + uu], U[j * NC + NU + uu], U[j * NC + 2 * NU + uu], 0.f);
    }
    for (int idx = tid; idx < 4 * NU; idx += 128)
        (&hmpk[0][0])[idx] = make_float4(0.f, 0.f, 0.f, 0.f);

    float br0 = 0.f, br1 = 0.f, br2 = 0.f, wdu = 0.f;
    float rdp_f[2][3];
    float hreg[2] = {0.f, 0.f};
    float xz[2], xr[2], xh[2];
    const int fr0  = 2 * s;          // rows this group finalizes
    const int orow = 2 * (1 - s);    // rows whose partials we hand over

    if (active) {
        br0 = bb[NC + u]; br1 = bb[NC + NU + u]; br2 = bb[NC + 2 * NU + u];
        wdu = Wd[u];
        #pragma unroll
        for (int i = 0; i < 2; ++i)
            #pragma unroll
            for (int g = 0; g < 3; ++g)
                rdp_f[i][g] = rdp[g * (B_ * NU) + (b0 + fr0 + i) * NU + u];
        #pragma unroll
        for (int i = 0; i < 2; ++i) {
            const float* Xp = g_X + ((size_t)(b0 + fr0 + i) * T_) * XP;
            xz[i] = Xp[u]; xr[i] = Xp[NU + u]; xh[i] = Xp[2 * NU + u];
        }
    }
    const int jbeg = s * 25;
    __syncthreads();

    for (int t = 0; t < T_; ++t) {
        float az[4] = {0,0,0,0}, ar[4] = {0,0,0,0}, ah[4] = {0,0,0,0};
        if (active) {
            #pragma unroll 5
            for (int j = jbeg; j < jbeg + 25; ++j) {
                float4 Uc = Upk[j * NU + u];
                #pragma unroll
                for (int r = 0; r < 4; ++r) {
                    float4 hm = hmpk[r][j];
                    az[r] = fmaf(hm.x, Uc.x, az[r]);
                    ar[r] = fmaf(hm.y, Uc.y, ar[r]);
                    ah[r] = fmaf(hm.z, Uc.z, ah[r]);
                }
            }
            part[orow][u]     = make_float4(az[orow],     ar[orow],     ah[orow],     0.f);
            part[orow + 1][u] = make_float4(az[orow + 1], ar[orow + 1], ah[orow + 1], 0.f);
        }
        __syncthreads();
        if (active) {
            const int tn = (t < T_ - 1) ? t + 1 : t;
            #pragma unroll
            for (int i = 0; i < 2; ++i) {
                const int r = fr0 + i;
                float4 p = part[r][u];
                float AZ = az[r] + p.x;
                float AR = ar[r] + p.y;
                float AH = ah[r] + p.z;
                float zz = sigm(xz[i] + AZ + br0);
                float rr = sigm(xr[i] + AR + br1);
                float hh = tanh_fast(xh[i] + rr * (AH + br2));
                float hn = zz * hreg[i] + (1.f - zz) * hh;
                hreg[i] = hn;
                hmpk[r][u] = make_float4(hn * rdp_f[i][0], hn * rdp_f[i][1], hn * rdp_f[i][2], hn);
                // prefetch next timestep's projected inputs
                const float* Xp = g_X + ((size_t)(b0 + r) * T_ + tn) * XP;
                xz[i] = Xp[u]; xr[i] = Xp[NU + u]; xh[i] = Xp[2 * NU + u];
            }
        }
        __syncthreads();
    }

    // dense head: out[b] = h . Wd + bd
    if (active) {
        part[fr0][u].x     = hreg[0] * wdu;
        part[fr0 + 1][u].x = hreg[1] * wdu;
    }
    __syncthreads();
    if (tid < 4) {
        float sum = 0.f;
        for (int uu = 0; uu < NU; ++uu) sum += part[tid][uu].x;
        out[b0 + tid] = sum + bd[0];
    }
}

// ---------------- launch ----------------
extern "C" void kernel_launch(void* const* d_in, const int* in_sizes, int n_in,
                              void* d_out, int out_size)
{
    const float* inp = (const float*)d_in[0];
    const float* W   = (const float*)d_in[1];
    const float* U   = (const float*)d_in[2];
    const float* bb  = (const float*)d_in[3];
    const float* Wd  = (const float*)d_in[4];
    const float* bd  = (const float*)d_in[5];
    const float* dp  = (const float*)d_in[6];
    const float* rdp = (const float*)d_in[7];
    float* out = (float*)d_out;

    cudaFuncSetAttribute(xproj_kernel, cudaFuncAttributeMaxDynamicSharedMemorySize, SMEM_XPROJ);
    xproj_kernel<<<B_, 256, SMEM_XPROJ>>>(inp, W, bb, dp);
    scan_kernel<<<B_ / 4, 128>>>(U, bb, Wd, bd, rdp, out);
}

// round 2
// speedup vs baseline: 1.1263x; 1.1263x over previous
#include <cuda_runtime.h>

#define B_  512
#define T_  512
#define F_  128
#define NU  50
#define NC  150   // 3*NU
#define XP  160   // padded X row (floats)

// Scratch for projected inputs X[b][t][160] (cols 150..159 unused garbage).
__device__ float g_X[(size_t)B_ * T_ * XP];

typedef unsigned long long ull;

// ---------------- packed f32x2 helpers ----------------
__device__ __forceinline__ ull dup2(float x) {
    ull r;
    asm("mov.b64 %0, {%1, %1};" : "=l"(r) : "f"(x));
    return r;
}
__device__ __forceinline__ void fma2(ull& d, ull a, ull b) {
    asm("fma.rn.f32x2 %0, %1, %2, %0;" : "+l"(d) : "l"(a), "l"(b));
}
__device__ __forceinline__ void unpack2(ull v, float& lo, float& hi) {
    asm("mov.b64 {%0, %1}, %2;" : "=f"(lo), "=f"(hi) : "l"(v));
}

__device__ __forceinline__ float sigm(float x) {
    return __fdividef(1.f, 1.f + __expf(-x));
}
__device__ __forceinline__ float tanh_fast(float x) {
    return __fdividef(2.f, 1.f + __expf(-2.f * x)) - 1.f;
}

// ---------------- Kernel 1: input projection ----------------
// One CTA per batch element b. Weff[k][c] = W[k][c]*dp[c/50][b][k] in smem.
// Register tile per thread: 8 rows x 10 cols (5 col-PAIRS, interleaved so a
// warp's W loads are contiguous 128B lines). 40 fma.rn.f32x2 per k.
#define RT    128            // rows (timesteps) per tile
#define AS    129            // odd stride for transposed A (conflict-free STS)
#define SM_W  (F_ * XP)      // 20480 floats
#define SM_B  (XP)           // 160
#define SM_A  (F_ * AS)      // 16512
#define SMEM_XPROJ ((SM_W + SM_B + SM_A) * 4)   // ~148.6 KB

__global__ void __launch_bounds__(256, 1) xproj_kernel(
    const float* __restrict__ inp, const float* __restrict__ W,
    const float* __restrict__ bb, const float* __restrict__ dp)
{
    extern __shared__ float sm[];
    float* Weff = sm;              // [128][160]
    float* bi_s = sm + SM_W;       // [160]
    float* A_s  = bi_s + SM_B;     // [128][129]  (k-major, transposed tile)

    const int b   = blockIdx.x;
    const int tid = threadIdx.x;

    // Masked weights for this batch element (+ zero pad cols 150..159)
    for (int idx = tid; idx < F_ * XP; idx += 256) {
        int k = idx / XP, c = idx - k * XP;
        float w = 0.f;
        if (c < NC) w = W[k * NC + c] * dp[(c / NU) * (B_ * F_) + b * F_ + k];
        Weff[idx] = w;
    }
    for (int c = tid; c < XP; c += 256)
        bi_s[c] = (c < NC) ? bb[c] : 0.f;

    const int cx = tid & 15;       // col-pair lane: pairs {j*16+cx, j<5}
    const int ry = tid >> 4;       // row group: rows ry*8 .. ry*8+7
    const int r0 = ry * 8;
    const ull* Wv = reinterpret_cast<const ull*>(Weff);
    const ull* bv = reinterpret_cast<const ull*>(bi_s);

    for (int tile = 0; tile < T_ / RT; ++tile) {
        const int t0 = tile * RT;
        __syncthreads();   // protect A_s reuse (covers Weff build on tile 0)
        const float* src = inp + ((size_t)b * T_ + t0) * F_;
        for (int idx = tid; idx < RT * F_; idx += 256) {
            int r = idx >> 7, k = idx & 127;
            A_s[k * AS + r] = src[idx];      // coalesced LDG, odd-stride STS
        }
        __syncthreads();

        ull acc[8][5];
        #pragma unroll
        for (int i = 0; i < 8; ++i)
            #pragma unroll
            for (int j = 0; j < 5; ++j)
                acc[i][j] = bv[j * 16 + cx];

        #pragma unroll 2
        for (int k = 0; k < F_; ++k) {
            ull w[5];
            #pragma unroll
            for (int j = 0; j < 5; ++j)
                w[j] = Wv[k * (XP / 2) + j * 16 + cx];   // contiguous per warp
            #pragma unroll
            for (int i = 0; i < 8; ++i) {
                ull ad = dup2(A_s[k * AS + r0 + i]);     // broadcast
                #pragma unroll
                for (int j = 0; j < 5; ++j)
                    fma2(acc[i][j], ad, w[j]);
            }
        }

        #pragma unroll
        for (int i = 0; i < 8; ++i) {
            ull* Xr = reinterpret_cast<ull*>(g_X + ((size_t)b * T_ + t0 + r0 + i) * XP);
            #pragma unroll
            for (int j = 0; j < 5; ++j)
                Xr[j * 16 + cx] = acc[i][j];
        }
    }
}

// ---------------- Kernel 2: recurrent scan ----------------
// 128 CTAs x 4 batch rows, 256 threads: u = tid&63 (unit), s = tid>>6 (j-quarter
// AND the row this thread finalizes). U kept DUPLICATED in registers (f32x2);
// hm4[g][j] = float4 of the 4 rows' masked h -> rows packed 2-wide in fma2.
#define JSEG 13
#define JPAD 52   // 4*JSEG, entries >= 50 stay zero

__global__ void __launch_bounds__(256, 1) scan_kernel(
    const float* __restrict__ U, const float* __restrict__ bb,
    const float* __restrict__ Wd, const float* __restrict__ bd,
    const float* __restrict__ rdp, float* __restrict__ out)
{
    __shared__ float4 hm4[3][JPAD];       // [gate][j] = {h0m,h1m,h2m,h3m}
    __shared__ float4 part[4][4][64];     // [writer s][row][u] = {z,r,h,_}

    const int tid = threadIdx.x;
    const int u   = tid & 63;
    const int s   = tid >> 6;             // j-quarter; also the row finalized
    const int b0  = blockIdx.x * 4;
    const bool active = (u < NU);
    const int jbeg = s * JSEG;

    for (int idx = tid; idx < 3 * JPAD; idx += 256)
        (&hm4[0][0])[idx] = make_float4(0.f, 0.f, 0.f, 0.f);

    // U slice, duplicated for packed-row fma2
    ull Uzd[JSEG], Urd[JSEG], Uhd[JSEG];
    #pragma unroll
    for (int jj = 0; jj < JSEG; ++jj) {
        int j = jbeg + jj;
        float vz = 0.f, vr = 0.f, vh = 0.f;
        if (active && j < NU) {
            vz = U[j * NC + u];
            vr = U[j * NC + NU + u];
            vh = U[j * NC + 2 * NU + u];
        }
        Uzd[jj] = dup2(vz); Urd[jj] = dup2(vr); Uhd[jj] = dup2(vh);
    }

    float br0 = 0.f, br1 = 0.f, br2 = 0.f, wdu = 0.f;
    float rdp0 = 0.f, rdp1 = 0.f, rdp2 = 0.f;
    float xz = 0.f, xr = 0.f, xh = 0.f, h = 0.f;
    const float* Xrow = g_X + (size_t)(b0 + s) * T_ * XP;
    if (active) {
        br0 = bb[NC + u]; br1 = bb[NC + NU + u]; br2 = bb[NC + 2 * NU + u];
        wdu = Wd[u];
        rdp0 = rdp[0 * (B_ * NU) + (b0 + s) * NU + u];
        rdp1 = rdp[1 * (B_ * NU) + (b0 + s) * NU + u];
        rdp2 = rdp[2 * (B_ * NU) + (b0 + s) * NU + u];
        xz = Xrow[u]; xr = Xrow[NU + u]; xh = Xrow[2 * NU + u];
    }
    __syncthreads();

    for (int t = 0; t < T_; ++t) {
        ull aZ0 = 0, aZ1 = 0, aR0 = 0, aR1 = 0, aH0 = 0, aH1 = 0;
        const ulonglong2* h0p = reinterpret_cast<const ulonglong2*>(&hm4[0][jbeg]);
        const ulonglong2* h1p = reinterpret_cast<const ulonglong2*>(&hm4[1][jbeg]);
        const ulonglong2* h2p = reinterpret_cast<const ulonglong2*>(&hm4[2][jbeg]);
        #pragma unroll
        for (int jj = 0; jj < JSEG; ++jj) {
            ulonglong2 va = h0p[jj];   // broadcast: rows {0,1} / {2,3}
            ulonglong2 vb = h1p[jj];
            ulonglong2 vc = h2p[jj];
            fma2(aZ0, va.x, Uzd[jj]); fma2(aZ1, va.y, Uzd[jj]);
            fma2(aR0, vb.x, Urd[jj]); fma2(aR1, vb.y, Urd[jj]);
            fma2(aH0, vc.x, Uhd[jj]); fma2(aH1, vc.y, Uhd[jj]);
        }
        float zf[4], rf[4], hf[4];
        unpack2(aZ0, zf[0], zf[1]); unpack2(aZ1, zf[2], zf[3]);
        unpack2(aR0, rf[0], rf[1]); unpack2(aR1, rf[2], rf[3]);
        unpack2(aH0, hf[0], hf[1]); unpack2(aH1, hf[2], hf[3]);
        #pragma unroll
        for (int r = 0; r < 4; ++r)
            if (r != s) part[s][r][u] = make_float4(zf[r], rf[r], hf[r], 0.f);
        __syncthreads();

        if (active) {
            float sz = zf[s], sr = rf[s], sh = hf[s];
            #pragma unroll
            for (int q = 1; q < 4; ++q) {
                int sp = (s + q) & 3;
                float4 p = part[sp][s][u];
                sz += p.x; sr += p.y; sh += p.z;
            }
            float z  = sigm(xz + sz + br0);
            float r  = sigm(xr + sr + br1);
            float hh = tanh_fast(xh + r * (sh + br2));
            h = z * h + (1.f - z) * hh;
            float* hb = (float*)hm4;
            hb[(0 * JPAD + u) * 4 + s] = h * rdp0;
            hb[(1 * JPAD + u) * 4 + s] = h * rdp1;
            hb[(2 * JPAD + u) * 4 + s] = h * rdp2;
            // prefetch next timestep's projected inputs
            int tn = (t < T_ - 1) ? t + 1 : t;
            const float* Xp = Xrow + (size_t)tn * XP;
            xz = Xp[u]; xr = Xp[NU + u]; xh = Xp[2 * NU + u];
        }
        __syncthreads();
    }

    // dense head: out[b] = h . Wd + bd
    if (active) part[0][s][u].x = h * wdu;
    __syncthreads();
    if (tid < 4) {
        float sum = bd[0];
        for (int uu = 0; uu < NU; ++uu) sum += part[0][tid][uu].x;
        out[b0 + tid] = sum;
    }
}

// ---------------- launch ----------------
extern "C" void kernel_launch(void* const* d_in, const int* in_sizes, int n_in,
                              void* d_out, int out_size)
{
    const float* inp = (const float*)d_in[0];
    const float* W   = (const float*)d_in[1];
    const float* U   = (const float*)d_in[2];
    const float* bb  = (const float*)d_in[3];
    const float* Wd  = (const float*)d_in[4];
    const float* bd  = (const float*)d_in[5];
    const float* dp  = (const float*)d_in[6];
    const float* rdp = (const float*)d_in[7];
    float* out = (float*)d_out;

    cudaFuncSetAttribute(xproj_kernel, cudaFuncAttributeMaxDynamicSharedMemorySize, SMEM_XPROJ);
    xproj_kernel<<<B_, 256, SMEM_XPROJ>>>(inp, W, bb, dp);
    scan_kernel<<<B_ / 4, 256>>>(U, bb, Wd, bd, rdp, out);
}

// round 3
// speedup vs baseline: 1.4182x; 1.2591x over previous
#include <cuda_runtime.h>
#include <cstdint>

#define B_  512
#define T_  512
#define F_  128
#define NU  50
#define NC  150   // 3*NU
#define XP  160   // padded X row (floats)

// Scratch for projected inputs X[b][t][160] (cols 150..159 unused garbage).
__device__ float g_X[(size_t)B_ * T_ * XP];

typedef unsigned long long ull;

// ---------------- packed f32x2 helpers ----------------
__device__ __forceinline__ ull dup2(float x) {
    ull r;
    asm("mov.b64 %0, {%1, %1};" : "=l"(r) : "f"(x));
    return r;
}
__device__ __forceinline__ void fma2(ull& d, ull a, ull b) {
    asm("fma.rn.f32x2 %0, %1, %2, %0;" : "+l"(d) : "l"(a), "l"(b));
}
__device__ __forceinline__ void unpack2(ull v, float& lo, float& hi) {
    asm("mov.b64 {%0, %1}, %2;" : "=f"(lo), "=f"(hi) : "l"(v));
}

__device__ __forceinline__ float sigm(float x) {
    return __fdividef(1.f, 1.f + __expf(-x));
}
__device__ __forceinline__ float tanh_fast(float x) {
    return __fdividef(2.f, 1.f + __expf(-2.f * x)) - 1.f;
}

__device__ __forceinline__ uint32_t smem_u32(const void* p) {
    uint32_t a;
    asm("{ .reg .u64 t; cvta.to.shared.u64 t, %1; cvt.u32.u64 %0, t; }"
        : "=r"(a) : "l"(p));
    return a;
}

// ---------------- Kernel 1: input projection ----------------
// One CTA (512 threads) per batch element b. Weff[k][c] = W[k][c]*dp[c/50][b][k].
// Register tile per thread: 4 rows x 10 cols (5 interleaved col-pairs);
// 20 fma.rn.f32x2 per k. 16 warps = 4/SMSP for latency hiding.
#define RT    128            // rows (timesteps) per tile
#define AS    129            // odd stride for transposed A (conflict-free STS)
#define SM_W  (F_ * XP)      // 20480 floats
#define SM_B  (XP)           // 160
#define SM_A  (F_ * AS)      // 16512
#define SMEM_XPROJ ((SM_W + SM_B + SM_A) * 4)   // ~148.6 KB

__global__ void __launch_bounds__(512, 1) xproj_kernel(
    const float* __restrict__ inp, const float* __restrict__ W,
    const float* __restrict__ bb, const float* __restrict__ dp)
{
    extern __shared__ float sm[];
    float* Weff = sm;              // [128][160]
    float* bi_s = sm + SM_W;       // [160]
    float* A_s  = bi_s + SM_B;     // [128][129]  (k-major, transposed tile)

    const int b   = blockIdx.x;
    const int tid = threadIdx.x;

    // Masked weights for this batch element (+ zero pad cols 150..159)
    for (int idx = tid; idx < F_ * XP; idx += 512) {
        int k = idx / XP, c = idx - k * XP;
        float w = 0.f;
        if (c < NC) w = W[k * NC + c] * dp[(c / NU) * (B_ * F_) + b * F_ + k];
        Weff[idx] = w;
    }
    for (int c = tid; c < XP; c += 512)
        bi_s[c] = (c < NC) ? bb[c] : 0.f;

    const int cx = tid & 15;       // col-pair lane: pairs {j*16+cx, j<5}
    const int ry = tid >> 4;       // row group 0..31: rows ry*4 .. ry*4+3
    const int r0 = ry * 4;
    const ull* Wv = reinterpret_cast<const ull*>(Weff);
    const ull* bv = reinterpret_cast<const ull*>(bi_s);

    for (int tile = 0; tile < T_ / RT; ++tile) {
        const int t0 = tile * RT;
        __syncthreads();   // protect A_s reuse (covers Weff build on tile 0)
        const float* src = inp + ((size_t)b * T_ + t0) * F_;
        for (int idx = tid; idx < RT * F_; idx += 512) {
            int r = idx >> 7, k = idx & 127;
            A_s[k * AS + r] = src[idx];      // coalesced LDG, odd-stride STS
        }
        __syncthreads();

        ull acc[4][5];
        #pragma unroll
        for (int i = 0; i < 4; ++i)
            #pragma unroll
            for (int j = 0; j < 5; ++j)
                acc[i][j] = bv[j * 16 + cx];

        #pragma unroll 2
        for (int k = 0; k < F_; ++k) {
            ull w[5];
            #pragma unroll
            for (int j = 0; j < 5; ++j)
                w[j] = Wv[k * (XP / 2) + j * 16 + cx];   // contiguous per half-warp
            #pragma unroll
            for (int i = 0; i < 4; ++i) {
                ull ad = dup2(A_s[k * AS + r0 + i]);     // broadcast
                #pragma unroll
                for (int j = 0; j < 5; ++j)
                    fma2(acc[i][j], ad, w[j]);
            }
        }

        #pragma unroll
        for (int i = 0; i < 4; ++i) {
            ull* Xr = reinterpret_cast<ull*>(g_X + ((size_t)b * T_ + t0 + r0 + i) * XP);
            #pragma unroll
            for (int j = 0; j < 5; ++j)
                Xr[j * 16 + cx] = acc[i][j];
        }
    }
}

// ---------------- Kernel 2: recurrent scan ----------------
// 128 CTAs x 4 batch rows, 256 threads: u = tid&63, s = tid>>6 (j-quarter AND
// the row this thread finalizes). U duplicated in registers (f32x2); rows
// packed 2-wide via hm4[g][j] = float4{h0m,h1m,h2m,h3m}. X staged through a
// cp.async double buffer (8 steps x 4 rows per chunk) -> no LDG in step loop.
#define JSEG 13
#define JPAD 52   // 4*JSEG, entries >= 50 stay zero
#define CH   8                       // steps per chunk
#define XQ   38                      // float4 per (row,step): 152 floats >= 150
#define CHUNK_F4 (4 * CH * XQ)       // 1216 float4 per chunk

__global__ void __launch_bounds__(256, 1) scan_kernel(
    const float* __restrict__ U, const float* __restrict__ bb,
    const float* __restrict__ Wd, const float* __restrict__ bd,
    const float* __restrict__ rdp, float* __restrict__ out)
{
    __shared__ float4 hm4[3][JPAD];        // [gate][j] = {h0m,h1m,h2m,h3m}
    __shared__ float4 part[4][4][64];      // [writer s][row][u] = {z,r,h,_}
    __shared__ float4 Xs[2][4][CH][XQ];    // double-buffered X chunks

    const int tid = threadIdx.x;
    const int u   = tid & 63;
    const int s   = tid >> 6;              // j-quarter; also the row finalized
    const int b0  = blockIdx.x * 4;
    const bool active = (u < NU);
    const int jbeg = s * JSEG;

    for (int idx = tid; idx < 3 * JPAD; idx += 256)
        (&hm4[0][0])[idx] = make_float4(0.f, 0.f, 0.f, 0.f);

    // U slice, duplicated for packed-row fma2
    ull Uzd[JSEG], Urd[JSEG], Uhd[JSEG];
    #pragma unroll
    for (int jj = 0; jj < JSEG; ++jj) {
        int j = jbeg + jj;
        float vz = 0.f, vr = 0.f, vh = 0.f;
        if (active && j < NU) {
            vz = U[j * NC + u];
            vr = U[j * NC + NU + u];
            vh = U[j * NC + 2 * NU + u];
        }
        Uzd[jj] = dup2(vz); Urd[jj] = dup2(vr); Uhd[jj] = dup2(vh);
    }

    float br0 = 0.f, br1 = 0.f, br2 = 0.f, wdu = 0.f;
    float rdp0 = 0.f, rdp1 = 0.f, rdp2 = 0.f, h = 0.f;
    if (active) {
        br0 = bb[NC + u]; br1 = bb[NC + NU + u]; br2 = bb[NC + 2 * NU + u];
        wdu = Wd[u];
        rdp0 = rdp[0 * (B_ * NU) + (b0 + s) * NU + u];
        rdp1 = rdp[1 * (B_ * NU) + (b0 + s) * NU + u];
        rdp2 = rdp[2 * (B_ * NU) + (b0 + s) * NU + u];
    }

    // ---- cp.async chunk loader (all 256 threads) ----
    const uint32_t xs_base = smem_u32(&Xs[0][0][0][0]);
    auto issue_chunk = [&](int c, int buf) {
        #pragma unroll
        for (int it = 0; it < 5; ++it) {
            int lin = it * 256 + tid;
            if (lin < CHUNK_F4) {
                int r   = lin / (CH * XQ);
                int rem = lin - r * (CH * XQ);
                int tt  = rem / XQ;
                int q   = rem - tt * XQ;
                const float* g = g_X + ((size_t)(b0 + r) * T_ + c * CH + tt) * XP + q * 4;
                uint32_t dst = xs_base + (uint32_t)(((buf * 4 + r) * CH + tt) * XQ + q) * 16u;
                asm volatile("cp.async.cg.shared.global [%0], [%1], 16;"
                             :: "r"(dst), "l"(g) : "memory");
            }
        }
        asm volatile("cp.async.commit_group;" ::: "memory");
    };

    issue_chunk(0, 0);
    issue_chunk(1, 1);
    asm volatile("cp.async.wait_group 1;" ::: "memory");   // chunk 0 ready
    __syncthreads();

    const int NCHUNK = T_ / CH;   // 64
    for (int c = 0; c < NCHUNK; ++c) {
        const int buf = c & 1;
        const float* Xrow = reinterpret_cast<const float*>(&Xs[buf][s][0][0]);

        for (int tt = 0; tt < CH; ++tt) {
            // phase A: read x (smem), compute split-K partials
            float xz = 0.f, xr = 0.f, xh = 0.f;
            if (active) {
                const float* Xp = Xrow + tt * (XQ * 4);
                xz = Xp[u]; xr = Xp[NU + u]; xh = Xp[2 * NU + u];
            }
            ull aZ0 = 0, aZ1 = 0, aR0 = 0, aR1 = 0, aH0 = 0, aH1 = 0;
            const ulonglong2* h0p = reinterpret_cast<const ulonglong2*>(&hm4[0][jbeg]);
            const ulonglong2* h1p = reinterpret_cast<const ulonglong2*>(&hm4[1][jbeg]);
            const ulonglong2* h2p = reinterpret_cast<const ulonglong2*>(&hm4[2][jbeg]);
            #pragma unroll
            for (int jj = 0; jj < JSEG; ++jj) {
                ulonglong2 va = h0p[jj];   // rows {0,1} / {2,3}
                ulonglong2 vb = h1p[jj];
                ulonglong2 vc = h2p[jj];
                fma2(aZ0, va.x, Uzd[jj]); fma2(aZ1, va.y, Uzd[jj]);
                fma2(aR0, vb.x, Urd[jj]); fma2(aR1, vb.y, Urd[jj]);
                fma2(aH0, vc.x, Uhd[jj]); fma2(aH1, vc.y, Uhd[jj]);
            }
            float zf[4], rf[4], hf[4];
            unpack2(aZ0, zf[0], zf[1]); unpack2(aZ1, zf[2], zf[3]);
            unpack2(aR0, rf[0], rf[1]); unpack2(aR1, rf[2], rf[3]);
            unpack2(aH0, hf[0], hf[1]); unpack2(aH1, hf[2], hf[3]);
            #pragma unroll
            for (int r = 0; r < 4; ++r)
                if (r != s) part[s][r][u] = make_float4(zf[r], rf[r], hf[r], 0.f);
            __syncthreads();

            // phase B: combine partials, activations, broadcast new h
            if (active) {
                float sz = zf[s], sr = rf[s], sh = hf[s];
                #pragma unroll
                for (int q = 1; q < 4; ++q) {
                    int sp = (s + q) & 3;
                    float4 p = part[sp][s][u];
                    sz += p.x; sr += p.y; sh += p.z;
                }
                float z  = sigm(xz + sz + br0);
                float r  = sigm(xr + sr + br1);
                float hh = tanh_fast(xh + r * (sh + br2));
                h = z * h + (1.f - z) * hh;
                float* hb = (float*)hm4;
                hb[(0 * JPAD + u) * 4 + s] = h * rdp0;
                hb[(1 * JPAD + u) * 4 + s] = h * rdp1;
                hb[(2 * JPAD + u) * 4 + s] = h * rdp2;
            }
            __syncthreads();
        }

        // chunk boundary: refill the buffer just consumed with chunk c+2
        if (c + 2 < NCHUNK) issue_chunk(c + 2, buf);
        asm volatile("cp.async.wait_group 1;" ::: "memory");  // chunk c+1 ready
        __syncthreads();
    }

    // dense head: out[b] = h . Wd + bd
    if (active) part[0][s][u].x = h * wdu;
    __syncthreads();
    if (tid < 4) {
        float sum = bd[0];
        for (int uu = 0; uu < NU; ++uu) sum += part[0][tid][uu].x;
        out[b0 + tid] = sum;
    }
}

// ---------------- launch ----------------
extern "C" void kernel_launch(void* const* d_in, const int* in_sizes, int n_in,
                              void* d_out, int out_size)
{
    const float* inp = (const float*)d_in[0];
    const float* W   = (const float*)d_in[1];
    const float* U   = (const float*)d_in[2];
    const float* bb  = (const float*)d_in[3];
    const float* Wd  = (const float*)d_in[4];
    const float* bd  = (const float*)d_in[5];
    const float* dp  = (const float*)d_in[6];
    const float* rdp = (const float*)d_in[7];
    float* out = (float*)d_out;

    cudaFuncSetAttribute(xproj_kernel, cudaFuncAttributeMaxDynamicSharedMemorySize, SMEM_XPROJ);
    xproj_kernel<<<B_, 512, SMEM_XPROJ>>>(inp, W, bb, dp);
    scan_kernel<<<B_ / 4, 256>>>(U, bb, Wd, bd, rdp, out);
}